// round 3
// baseline (speedup 1.0000x reference)
#include <cuda_runtime.h>

#define BB 2
#define HH 64
#define WW 64
#define CC 128
#define NHEAD 4
#define HD 32
#define KWIN 7
#define MROWS (BB*HH*WW)          /* 8192 */
#define SCALE 0.17677669529663687f /* 32^-0.5 */

// Scratch (allocation-free rule: device globals)
__device__ float g_q[MROWS*CC];
__device__ float g_k[MROWS*CC];
__device__ float g_v[MROWS*CC];
__device__ float g_att[MROWS*CC];

// ---------------------------------------------------------------------------
// Tiled fp32 GEMM v2: A[M,128] @ W[128,NTOT] + bias
// Tile 128x64, 256 threads, 8x4 per thread, K-chunk 16.
// MODE 0: split epilogue -> g_q (scaled), g_k, g_v   (NTOT=384), A = x
// MODE 1: out[row*NTOT+col] = val                    (NTOT=128), A = g_att
// ---------------------------------------------------------------------------
template<int NTOT, int MODE>
__global__ __launch_bounds__(256)
void gemm_k(const float* __restrict__ A,
            const float* __restrict__ W,
            const float* __restrict__ bias,
            float* __restrict__ out) {
    __shared__ float  As[16][132];  // transposed A tile [k][m], float4-aligned pad
    __shared__ float4 Bs[16][16];   // B tile [k][n/4]

    const float* Ap = (MODE == 1) ? (const float*)g_att : A;

    const int tid = threadIdx.x;
    const int tx  = tid & 15;       // col group (4 cols)
    const int ty  = tid >> 4;       // row group (8 rows)
    const int rowbase = blockIdx.x * 128;
    const int colbase = blockIdx.y * 64;

    const int arow  = tid >> 1;         // 0..127
    const int acolg = (tid & 1) * 8;    // 0 or 8
    const int brow  = tid >> 4;         // 0..15
    const int bcol  = tid & 15;         // 0..15

    float acc[8][4];
    #pragma unroll
    for (int i = 0; i < 8; ++i)
        #pragma unroll
        for (int j = 0; j < 4; ++j) acc[i][j] = 0.f;

    for (int k0 = 0; k0 < 128; k0 += 16) {
        const float* arowp = &Ap[(rowbase + arow) * 128 + k0 + acolg];
        float4 a0 = *(const float4*)arowp;
        float4 a1 = *(const float4*)(arowp + 4);
        As[acolg + 0][arow] = a0.x;
        As[acolg + 1][arow] = a0.y;
        As[acolg + 2][arow] = a0.z;
        As[acolg + 3][arow] = a0.w;
        As[acolg + 4][arow] = a1.x;
        As[acolg + 5][arow] = a1.y;
        As[acolg + 6][arow] = a1.z;
        As[acolg + 7][arow] = a1.w;
        Bs[brow][bcol] = *(const float4*)&W[(k0 + brow) * NTOT + colbase + bcol * 4];
        __syncthreads();

        #pragma unroll
        for (int kk = 0; kk < 16; ++kk) {
            float4 alo = *(const float4*)&As[kk][ty * 8];
            float4 ahi = *(const float4*)&As[kk][ty * 8 + 4];
            float4 b   = Bs[kk][tx];
            acc[0][0] += alo.x * b.x; acc[0][1] += alo.x * b.y; acc[0][2] += alo.x * b.z; acc[0][3] += alo.x * b.w;
            acc[1][0] += alo.y * b.x; acc[1][1] += alo.y * b.y; acc[1][2] += alo.y * b.z; acc[1][3] += alo.y * b.w;
            acc[2][0] += alo.z * b.x; acc[2][1] += alo.z * b.y; acc[2][2] += alo.z * b.z; acc[2][3] += alo.z * b.w;
            acc[3][0] += alo.w * b.x; acc[3][1] += alo.w * b.y; acc[3][2] += alo.w * b.z; acc[3][3] += alo.w * b.w;
            acc[4][0] += ahi.x * b.x; acc[4][1] += ahi.x * b.y; acc[4][2] += ahi.x * b.z; acc[4][3] += ahi.x * b.w;
            acc[5][0] += ahi.y * b.x; acc[5][1] += ahi.y * b.y; acc[5][2] += ahi.y * b.z; acc[5][3] += ahi.y * b.w;
            acc[6][0] += ahi.z * b.x; acc[6][1] += ahi.z * b.y; acc[6][2] += ahi.z * b.z; acc[6][3] += ahi.z * b.w;
            acc[7][0] += ahi.w * b.x; acc[7][1] += ahi.w * b.y; acc[7][2] += ahi.w * b.z; acc[7][3] += ahi.w * b.w;
        }
        __syncthreads();
    }

    #pragma unroll
    for (int i = 0; i < 8; ++i) {
        const int row = rowbase + ty * 8 + i;
        #pragma unroll
        for (int j = 0; j < 4; ++j) {
            const int col = colbase + tx * 4 + j;
            float v = acc[i][j] + bias[col];
            if (MODE == 0) {
                const int comp  = col >> 7;     // 0=q 1=k 2=v
                const int inner = col & 127;    // nh*32 + d
                if (comp == 0)      g_q[row * CC + inner] = v * SCALE;
                else if (comp == 1) g_k[row * CC + inner] = v;
                else                g_v[row * CC + inner] = v;
            } else {
                out[row * NTOT + col] = v;
            }
        }
    }
}

// ---------------------------------------------------------------------------
// Neighborhood attention v2: smem-tiled.
// Block = 8(w) x 6(h) pixel tile x 1 head. 6 warps; warp = one pixel row,
// lane = head dim. K/V halo (14w x 12h) cooperatively staged in smem.
// Logits are O(1) for this problem => plain exp (no max subtraction needed,
// fp32 exp overflows only beyond ~88).
// ---------------------------------------------------------------------------
#define TH 6
#define TW 8
#define HALO_H 12
#define HALO_W 14
#define NHALO (HALO_H*HALO_W)   /* 168 */

__global__ __launch_bounds__(192)
void natten_kernel(const float* __restrict__ rpb) {
    __shared__ float sk[NHALO * 32];
    __shared__ float sv[NHALO * 32];
    __shared__ float srp[169];

    const int tid  = threadIdx.x;
    const int lane = tid & 31;
    const int wid  = tid >> 5;

    const int w0 = blockIdx.x * TW;
    const int h0 = blockIdx.y * TH;
    const int nh = blockIdx.z & 3;
    const int b  = blockIdx.z >> 2;

    int gh0 = h0 - 3; gh0 = gh0 < 0 ? 0 : (gh0 > 64 - HALO_H ? 64 - HALO_H : gh0);
    int gw0 = w0 - 3; gw0 = gw0 < 0 ? 0 : (gw0 > 64 - HALO_W ? 64 - HALO_W : gw0);

    // Stage rpb table for this head
    for (int i = tid; i < 169; i += 192) srp[i] = rpb[nh * 169 + i];

    // Stage K/V halo: NHALO pixels x 8 float4 (32 floats) each
    const float4* gk4 = (const float4*)g_k;
    const float4* gv4 = (const float4*)g_v;
    float4* sk4 = (float4*)sk;
    float4* sv4 = (float4*)sv;
    const int bbase = b << 12;
    for (int i = tid; i < NHALO * 8; i += 192) {
        const int p = i >> 3;
        const int f = i & 7;
        const int r = p / HALO_W;
        const int c = p - r * HALO_W;
        const int gp = bbase + ((gh0 + r) << 6) + gw0 + c;      // pixel index
        const int goff = gp * 32 + nh * 8 + f;                   // float4 index
        sk4[i] = gk4[goff];
        sv4[i] = gv4[goff];
    }
    __syncthreads();

    const int h = h0 + wid;
    if (h >= 64) return;

    int hs = h - 3; hs = hs < 0 ? 0 : (hs > 57 ? 57 : hs);
    const int rh = hs - gh0;

    #pragma unroll
    for (int j = 0; j < TW; ++j) {
        const int w = w0 + j;
        int ws = w - 3; ws = ws < 0 ? 0 : (ws > 57 ? 57 : ws);
        const int rw = ws - gw0;

        const int pixoff = ((bbase + (h << 6) + w) << 7) + (nh << 5) + lane;
        const float qd = g_q[pixoff];                 // already *SCALE
        const int bb = (hs - h + 6) * 13 + (ws - w + 6);

        float l = 0.f, acc = 0.f;
        #pragma unroll
        for (int p = 0; p < KWIN; ++p) {
            const int rowoff = ((rh + p) * HALO_W + rw) << 5;
            #pragma unroll
            for (int q = 0; q < KWIN; ++q) {
                const int si = rowoff + (q << 5) + lane;
                float s = qd * sk[si];
                s += __shfl_xor_sync(0xffffffffu, s, 16);
                s += __shfl_xor_sync(0xffffffffu, s, 8);
                s += __shfl_xor_sync(0xffffffffu, s, 4);
                s += __shfl_xor_sync(0xffffffffu, s, 2);
                s += __shfl_xor_sync(0xffffffffu, s, 1);
                const float e = __expf(s + srp[bb + p * 13 + q]);
                l   += e;
                acc += e * sv[si];
            }
        }
        g_att[pixoff] = acc / l;
    }
}

extern "C" void kernel_launch(void* const* d_in, const int* in_sizes, int n_in,
                              void* d_out, int out_size) {
    (void)in_sizes; (void)n_in; (void)out_size;
    const float* x      = (const float*)d_in[0];
    const float* w_qkv  = (const float*)d_in[1];
    const float* b_qkv  = (const float*)d_in[2];
    const float* rpb    = (const float*)d_in[3];
    const float* w_proj = (const float*)d_in[4];
    const float* b_proj = (const float*)d_in[5];
    float* out = (float*)d_out;

    dim3 g1(MROWS / 128, 384 / 64);
    gemm_k<384, 0><<<g1, 256>>>(x, w_qkv, b_qkv, nullptr);

    dim3 gn(WW / TW, (HH + TH - 1) / TH, BB * NHEAD);   // (8, 11, 8)
    natten_kernel<<<gn, 192>>>(rpb);

    dim3 g2(MROWS / 128, 128 / 64);
    gemm_k<128, 1><<<g2, 256>>>(nullptr, w_proj, b_proj, out);
}

// round 5
// speedup vs baseline: 1.3710x; 1.3710x over previous
#include <cuda_runtime.h>

#define BB 2
#define HH 64
#define WW 64
#define CC 128
#define NHEAD 4
#define HD 32
#define KWIN 7
#define MROWS (BB*HH*WW)          /* 8192 */
#define SCALE 0.17677669529663687f /* 32^-0.5 */

// Scratch (allocation-free rule: device globals)
__device__ float g_q[MROWS*CC];
__device__ float g_k[MROWS*CC];
__device__ float g_v[MROWS*CC];
__device__ float g_att[MROWS*CC];

// ---------------------------------------------------------------------------
// Tiled fp32 GEMM: A[M,128] @ W[128,NTOT] + bias
// Tile 128x64, 256 threads, 8x4 per thread, K-chunk 16.
// MODE 0: split epilogue -> g_q (scaled), g_k, g_v   (NTOT=384), A = x
// MODE 1: out[row*NTOT+col] = val                    (NTOT=128), A = g_att
// ---------------------------------------------------------------------------
template<int NTOT, int MODE>
__global__ __launch_bounds__(256)
void gemm_k(const float* __restrict__ A,
            const float* __restrict__ W,
            const float* __restrict__ bias,
            float* __restrict__ out) {
    __shared__ __align__(16) float  As[16][132];
    __shared__ float4 Bs[16][16];

    const float* Ap = (MODE == 1) ? (const float*)g_att : A;

    const int tid = threadIdx.x;
    const int tx  = tid & 15;
    const int ty  = tid >> 4;
    const int rowbase = blockIdx.x * 128;
    const int colbase = blockIdx.y * 64;

    const int arow  = tid >> 1;
    const int acolg = (tid & 1) * 8;
    const int brow  = tid >> 4;
    const int bcol  = tid & 15;

    float acc[8][4];
    #pragma unroll
    for (int i = 0; i < 8; ++i)
        #pragma unroll
        for (int j = 0; j < 4; ++j) acc[i][j] = 0.f;

    for (int k0 = 0; k0 < 128; k0 += 16) {
        const float* arowp = &Ap[(rowbase + arow) * 128 + k0 + acolg];
        float4 a0 = *(const float4*)arowp;
        float4 a1 = *(const float4*)(arowp + 4);
        As[acolg + 0][arow] = a0.x;
        As[acolg + 1][arow] = a0.y;
        As[acolg + 2][arow] = a0.z;
        As[acolg + 3][arow] = a0.w;
        As[acolg + 4][arow] = a1.x;
        As[acolg + 5][arow] = a1.y;
        As[acolg + 6][arow] = a1.z;
        As[acolg + 7][arow] = a1.w;
        Bs[brow][bcol] = *(const float4*)&W[(k0 + brow) * NTOT + colbase + bcol * 4];
        __syncthreads();

        #pragma unroll
        for (int kk = 0; kk < 16; ++kk) {
            float4 alo = *(const float4*)&As[kk][ty * 8];
            float4 ahi = *(const float4*)&As[kk][ty * 8 + 4];
            float4 b   = Bs[kk][tx];
            acc[0][0] += alo.x * b.x; acc[0][1] += alo.x * b.y; acc[0][2] += alo.x * b.z; acc[0][3] += alo.x * b.w;
            acc[1][0] += alo.y * b.x; acc[1][1] += alo.y * b.y; acc[1][2] += alo.y * b.z; acc[1][3] += alo.y * b.w;
            acc[2][0] += alo.z * b.x; acc[2][1] += alo.z * b.y; acc[2][2] += alo.z * b.z; acc[2][3] += alo.z * b.w;
            acc[3][0] += alo.w * b.x; acc[3][1] += alo.w * b.y; acc[3][2] += alo.w * b.z; acc[3][3] += alo.w * b.w;
            acc[4][0] += ahi.x * b.x; acc[4][1] += ahi.x * b.y; acc[4][2] += ahi.x * b.z; acc[4][3] += ahi.x * b.w;
            acc[5][0] += ahi.y * b.x; acc[5][1] += ahi.y * b.y; acc[5][2] += ahi.y * b.z; acc[5][3] += ahi.y * b.w;
            acc[6][0] += ahi.z * b.x; acc[6][1] += ahi.z * b.y; acc[6][2] += ahi.z * b.z; acc[6][3] += ahi.z * b.w;
            acc[7][0] += ahi.w * b.x; acc[7][1] += ahi.w * b.y; acc[7][2] += ahi.w * b.z; acc[7][3] += ahi.w * b.w;
        }
        __syncthreads();
    }

    #pragma unroll
    for (int i = 0; i < 8; ++i) {
        const int row = rowbase + ty * 8 + i;
        #pragma unroll
        for (int j = 0; j < 4; ++j) {
            const int col = colbase + tx * 4 + j;
            float v = acc[i][j] + bias[col];
            if (MODE == 0) {
                const int comp  = col >> 7;
                const int inner = col & 127;
                if (comp == 0)      g_q[row * CC + inner] = v * SCALE;
                else if (comp == 1) g_k[row * CC + inner] = v;
                else                g_v[row * CC + inner] = v;
            } else {
                out[row * NTOT + col] = v;
            }
        }
    }
}

// ---------------------------------------------------------------------------
// Neighborhood attention v3.1: lane-per-neighbor, no per-neighbor shuffles.
// (v3 + 16B alignment on all shared arrays that are float4-cast)
// Block = 8(w) x 6(h) pixel tile x 1 head; warp = pixel row, 8 queries each.
// Phase A: lane n computes scores for neighbors n and n+32; q via float4 smem
//          broadcast, K rows stride-36 smem (16B-aligned) -> LDS.128.
//          2 exps per lane; one 5-shfl reduce per query for the denominator.
// Phase B: exps staged to smem rows of 8 -> float4 broadcast; lane = head dim
//          accumulates sum_n e_n * V_n[d], conflict-free.
// Logits are O(1) here => plain exp is safe in fp32.
// ---------------------------------------------------------------------------
#define TH 6
#define TW 8
#define HALO_H 12
#define HALO_W 14
#define NHALO (HALO_H*HALO_W)   /* 168 */
#define SKS 36                  /* padded K row stride (floats), 16B-aligned */

__global__ __launch_bounds__(192)
void natten_kernel(const float* __restrict__ rpb) {
    __shared__ float4 skq[NHALO * 9];                   // K halo
    __shared__ float4 svq[NHALO * 8];                   // V halo
    __shared__ __align__(16) float srp[176];            // rpb (169 used)
    __shared__ __align__(16) float sq[TH * 32];         // per-warp query
    __shared__ __align__(16) float se[TH * 64];         // per-warp exp(scores)

    float* skf = (float*)skq;
    float* svf = (float*)svq;

    const int tid  = threadIdx.x;
    const int lane = tid & 31;
    const int wid  = tid >> 5;

    const int w0 = blockIdx.x * TW;
    const int h0 = blockIdx.y * TH;
    const int nh = blockIdx.z & 3;
    const int b  = blockIdx.z >> 2;

    int gh0 = h0 - 3; gh0 = gh0 < 0 ? 0 : (gh0 > 64 - HALO_H ? 64 - HALO_H : gh0);
    int gw0 = w0 - 3; gw0 = gw0 < 0 ? 0 : (gw0 > 64 - HALO_W ? 64 - HALO_W : gw0);

    for (int i = tid; i < 169; i += 192) srp[i] = rpb[nh * 169 + i];

    const float4* gk4 = (const float4*)g_k;
    const float4* gv4 = (const float4*)g_v;
    const int bbase = b << 12;
    for (int i = tid; i < NHALO * 8; i += 192) {
        const int p = i >> 3;
        const int f = i & 7;
        const int r = p / HALO_W;
        const int c = p - r * HALO_W;
        const int gp = bbase + ((gh0 + r) << 6) + gw0 + c;   // pixel index
        const int goff = gp * 32 + nh * 8 + f;               // float4 index
        skq[p * 9 + f] = gk4[goff];
        svq[p * 8 + f] = gv4[goff];
    }
    __syncthreads();

    const int h = h0 + wid;
    if (h >= 64) return;

    int hs = h - 3; hs = hs < 0 ? 0 : (hs > 57 ? 57 : hs);
    const int rh = hs - gh0;

    // Per-lane neighbor mapping (fixed for all 8 queries of this warp)
    const int  n1  = lane + 32;
    const bool vd1 = (n1 < 49);
    const int  dp0 = lane / 7,            dq0 = lane - dp0 * 7;
    const int  dp1 = vd1 ? n1 / 7 : 0;
    const int  dq1 = vd1 ? n1 - dp1 * 7 : 0;
    const int  t0  = (dp0 * HALO_W + dq0) * SKS;
    const int  t1  = (dp1 * HALO_W + dq1) * SKS;
    const int  bt0 = dp0 * 13 + dq0;
    const int  bt1 = dp1 * 13 + dq1;
    const int  st0 = dp0 * 8 + dq0;
    const int  st1 = dp1 * 8 + dq1;

    float* seW = se + wid * 64;
    const float* sqW = sq + wid * 32;

    if (lane < 7) seW[lane * 8 + 7] = 0.f;   // zero pad slot (stays 0)
    __syncwarp();

    #pragma unroll
    for (int j = 0; j < TW; ++j) {
        const int w = w0 + j;
        int ws = w - 3; ws = ws < 0 ? 0 : (ws > 57 ? 57 : ws);
        const int rw = ws - gw0;

        const int pixoff = ((bbase + (h << 6) + w) << 7) + (nh << 5) + lane;
        sq[wid * 32 + lane] = g_q[pixoff];   // already *SCALE
        __syncwarp();

        // Phase A: two dot products per lane
        const int base = (rh * HALO_W + rw) * SKS;
        const float* k0p = skf + base + t0;
        const float* k1p = skf + base + t1;
        float s0 = 0.f, s1 = 0.f;
        #pragma unroll
        for (int d4 = 0; d4 < 8; ++d4) {
            float4 q4 = *(const float4*)(sqW + d4 * 4);
            float4 a  = *(const float4*)(k0p + d4 * 4);
            float4 c4 = *(const float4*)(k1p + d4 * 4);
            s0 += q4.x * a.x  + q4.y * a.y  + q4.z * a.z  + q4.w * a.w;
            s1 += q4.x * c4.x + q4.y * c4.y + q4.z * c4.z + q4.w * c4.w;
        }

        const int bbb = (hs - h + 6) * 13 + (ws - w + 6);
        const float e0 = __expf(s0 + srp[bbb + bt0]);
        const float e1 = vd1 ? __expf(s1 + srp[bbb + bt1]) : 0.f;

        float l = e0 + e1;
        l += __shfl_xor_sync(0xffffffffu, l, 16);
        l += __shfl_xor_sync(0xffffffffu, l, 8);
        l += __shfl_xor_sync(0xffffffffu, l, 4);
        l += __shfl_xor_sync(0xffffffffu, l, 2);
        l += __shfl_xor_sync(0xffffffffu, l, 1);

        seW[st0] = e0;
        if (vd1) seW[st1] = e1;
        __syncwarp();

        // Phase B: lane = head dim, accumulate over 49 neighbors
        float acc = 0.f;
        #pragma unroll
        for (int p = 0; p < KWIN; ++p) {
            const float* vr = svf + ((rh + p) * HALO_W + rw) * 32 + lane;
            float4 eA = *(const float4*)(seW + p * 8);
            float4 eB = *(const float4*)(seW + p * 8 + 4);
            acc += eA.x * vr[0]   + eA.y * vr[32]  + eA.z * vr[64]  + eA.w * vr[96]
                 + eB.x * vr[128] + eB.y * vr[160] + eB.z * vr[192];
        }
        g_att[pixoff] = acc / l;
        __syncwarp();
    }
}

extern "C" void kernel_launch(void* const* d_in, const int* in_sizes, int n_in,
                              void* d_out, int out_size) {
    (void)in_sizes; (void)n_in; (void)out_size;
    const float* x      = (const float*)d_in[0];
    const float* w_qkv  = (const float*)d_in[1];
    const float* b_qkv  = (const float*)d_in[2];
    const float* rpb    = (const float*)d_in[3];
    const float* w_proj = (const float*)d_in[4];
    const float* b_proj = (const float*)d_in[5];
    float* out = (float*)d_out;

    dim3 g1(MROWS / 128, 384 / 64);
    gemm_k<384, 0><<<g1, 256>>>(x, w_qkv, b_qkv, nullptr);

    dim3 gn(WW / TW, (HH + TH - 1) / TH, BB * NHEAD);   // (8, 11, 8)
    natten_kernel<<<gn, 192>>>(rpb);

    dim3 g2(MROWS / 128, 128 / 64);
    gemm_k<128, 1><<<g2, 256>>>(nullptr, w_proj, b_proj, out);
}

// round 6
// speedup vs baseline: 1.9577x; 1.4279x over previous
#include <cuda_runtime.h>

#define BB 2
#define HH 64
#define WW 64
#define CC 128
#define NHEAD 4
#define HD 32
#define KWIN 7
#define MROWS (BB*HH*WW)          /* 8192 */
#define SCALE 0.17677669529663687f /* 32^-0.5 */

// Scratch (allocation-free rule: device globals)
__device__ float g_q[MROWS*CC];
__device__ float g_k[MROWS*CC];
__device__ float g_v[MROWS*CC];
__device__ float g_att[MROWS*CC];

__device__ __forceinline__ unsigned f2tf(float f) {
    unsigned r;
    asm("cvt.rna.tf32.f32 %0, %1;" : "=r"(r) : "f"(f));
    return r;
}

__device__ __forceinline__ void mma_tf32(float c[4],
    unsigned a0, unsigned a1, unsigned a2, unsigned a3,
    unsigned b0, unsigned b1) {
    asm volatile(
        "mma.sync.aligned.m16n8k8.row.col.f32.tf32.tf32.f32 "
        "{%0,%1,%2,%3}, {%4,%5,%6,%7}, {%8,%9}, {%0,%1,%2,%3};"
        : "+f"(c[0]), "+f"(c[1]), "+f"(c[2]), "+f"(c[3])
        : "r"(a0), "r"(a1), "r"(a2), "r"(a3), "r"(b0), "r"(b1));
}

// ---------------------------------------------------------------------------
// tf32 tensor-core GEMM: A[M,128] @ W[128,NTOT] + bias
// Block tile 128x64, 256 threads = 8 warps (4M x 2N), warp tile 32x32.
// K staged in chunks of 32 (tf32-converted in smem).
// MODE 0: split epilogue -> g_q (scaled), g_k, g_v   (NTOT=384), A = x
// MODE 1: out[row*NTOT+col] = val                    (NTOT=128), A = g_att
// ---------------------------------------------------------------------------
template<int NTOT, int MODE>
__global__ __launch_bounds__(256)
void gemm_tc(const float* __restrict__ A,
             const float* __restrict__ W,
             const float* __restrict__ bias,
             float* __restrict__ out) {
    __shared__ __align__(16) unsigned As[128 * 36];  // [m][k], stride 36
    __shared__ __align__(16) unsigned Bs[32 * 72];   // [k][n], stride 72

    const float* Ap = (MODE == 1) ? (const float*)g_att : A;

    const int tid  = threadIdx.x;
    const int lane = tid & 31;
    const int wid  = tid >> 5;
    const int warpM = wid & 3;       // 0..3
    const int warpN = wid >> 2;      // 0..1
    const int grp = lane >> 2;       // 0..7
    const int tig = lane & 3;        // 0..3
    const int rowbase = blockIdx.x * 128;
    const int colbase = blockIdx.y * 64;

    float acc[2][4][4] = {};

    for (int kc = 0; kc < 4; ++kc) {
        const int k0 = kc * 32;
        // Stage A chunk [128 x 32] (coalesced: 8 threads per 128B row piece)
        #pragma unroll
        for (int j = 0; j < 4; ++j) {
            const int i = tid + j * 256;
            const int m  = i >> 3;
            const int kq = (i & 7) * 4;
            float4 v = *(const float4*)&Ap[(rowbase + m) * 128 + k0 + kq];
            uint4 u = make_uint4(f2tf(v.x), f2tf(v.y), f2tf(v.z), f2tf(v.w));
            *(uint4*)&As[m * 36 + kq] = u;
        }
        // Stage B chunk [32 x 64]
        #pragma unroll
        for (int j = 0; j < 2; ++j) {
            const int i = tid + j * 256;
            const int k  = i >> 4;
            const int nq = (i & 15) * 4;
            float4 v = *(const float4*)&W[(k0 + k) * NTOT + colbase + nq];
            uint4 u = make_uint4(f2tf(v.x), f2tf(v.y), f2tf(v.z), f2tf(v.w));
            *(uint4*)&Bs[k * 72 + nq] = u;
        }
        __syncthreads();

        #pragma unroll
        for (int ks = 0; ks < 4; ++ks) {
            const int kk = ks * 8;
            unsigned a[2][4], b[4][2];
            #pragma unroll
            for (int mf = 0; mf < 2; ++mf) {
                const int r = warpM * 32 + mf * 16 + grp;
                a[mf][0] = As[r * 36 + kk + tig];
                a[mf][1] = As[(r + 8) * 36 + kk + tig];
                a[mf][2] = As[r * 36 + kk + tig + 4];
                a[mf][3] = As[(r + 8) * 36 + kk + tig + 4];
            }
            #pragma unroll
            for (int nf = 0; nf < 4; ++nf) {
                const int c = warpN * 32 + nf * 8 + grp;
                b[nf][0] = Bs[(kk + tig) * 72 + c];
                b[nf][1] = Bs[(kk + tig + 4) * 72 + c];
            }
            #pragma unroll
            for (int mf = 0; mf < 2; ++mf)
                #pragma unroll
                for (int nf = 0; nf < 4; ++nf)
                    mma_tf32(acc[mf][nf],
                             a[mf][0], a[mf][1], a[mf][2], a[mf][3],
                             b[nf][0], b[nf][1]);
        }
        __syncthreads();
    }

    // Epilogue. D fragment: row = base+grp(+8), col = base+tig*2(+1)
    const int comp      = colbase >> 7;       // MODE 0: 0=q 1=k 2=v (uniform/block)
    const int innerbase = colbase & 127;
    #pragma unroll
    for (int mf = 0; mf < 2; ++mf) {
        #pragma unroll
        for (int nf = 0; nf < 4; ++nf) {
            const int colL = colbase + warpN * 32 + nf * 8 + tig * 2;
            const float bs0 = bias[colL];
            const float bs1 = bias[colL + 1];
            #pragma unroll
            for (int rr = 0; rr < 2; ++rr) {
                const int row = rowbase + warpM * 32 + mf * 16 + grp + rr * 8;
                float v0 = acc[mf][nf][rr * 2 + 0] + bs0;
                float v1 = acc[mf][nf][rr * 2 + 1] + bs1;
                if (MODE == 0) {
                    const int inner = innerbase + warpN * 32 + nf * 8 + tig * 2;
                    if (comp == 0) {
                        *(float2*)&g_q[row * CC + inner] = make_float2(v0 * SCALE, v1 * SCALE);
                    } else if (comp == 1) {
                        *(float2*)&g_k[row * CC + inner] = make_float2(v0, v1);
                    } else {
                        *(float2*)&g_v[row * CC + inner] = make_float2(v0, v1);
                    }
                } else {
                    *(float2*)&out[row * NTOT + colL] = make_float2(v0, v1);
                }
            }
        }
    }
}

// ---------------------------------------------------------------------------
// Neighborhood attention v3.1 (unchanged from Round 5 — measured win).
// ---------------------------------------------------------------------------
#define TH 6
#define TW 8
#define HALO_H 12
#define HALO_W 14
#define NHALO (HALO_H*HALO_W)   /* 168 */
#define SKS 36                  /* padded K row stride (floats), 16B-aligned */

__global__ __launch_bounds__(192)
void natten_kernel(const float* __restrict__ rpb) {
    __shared__ float4 skq[NHALO * 9];                   // K halo
    __shared__ float4 svq[NHALO * 8];                   // V halo
    __shared__ __align__(16) float srp[176];            // rpb (169 used)
    __shared__ __align__(16) float sq[TH * 32];         // per-warp query
    __shared__ __align__(16) float se[TH * 64];         // per-warp exp(scores)

    float* skf = (float*)skq;
    float* svf = (float*)svq;

    const int tid  = threadIdx.x;
    const int lane = tid & 31;
    const int wid  = tid >> 5;

    const int w0 = blockIdx.x * TW;
    const int h0 = blockIdx.y * TH;
    const int nh = blockIdx.z & 3;
    const int b  = blockIdx.z >> 2;

    int gh0 = h0 - 3; gh0 = gh0 < 0 ? 0 : (gh0 > 64 - HALO_H ? 64 - HALO_H : gh0);
    int gw0 = w0 - 3; gw0 = gw0 < 0 ? 0 : (gw0 > 64 - HALO_W ? 64 - HALO_W : gw0);

    for (int i = tid; i < 169; i += 192) srp[i] = rpb[nh * 169 + i];

    const float4* gk4 = (const float4*)g_k;
    const float4* gv4 = (const float4*)g_v;
    const int bbase = b << 12;
    for (int i = tid; i < NHALO * 8; i += 192) {
        const int p = i >> 3;
        const int f = i & 7;
        const int r = p / HALO_W;
        const int c = p - r * HALO_W;
        const int gp = bbase + ((gh0 + r) << 6) + gw0 + c;   // pixel index
        const int goff = gp * 32 + nh * 8 + f;               // float4 index
        skq[p * 9 + f] = gk4[goff];
        svq[p * 8 + f] = gv4[goff];
    }
    __syncthreads();

    const int h = h0 + wid;
    if (h >= 64) return;

    int hs = h - 3; hs = hs < 0 ? 0 : (hs > 57 ? 57 : hs);
    const int rh = hs - gh0;

    const int  n1  = lane + 32;
    const bool vd1 = (n1 < 49);
    const int  dp0 = lane / 7,            dq0 = lane - dp0 * 7;
    const int  dp1 = vd1 ? n1 / 7 : 0;
    const int  dq1 = vd1 ? n1 - dp1 * 7 : 0;
    const int  t0  = (dp0 * HALO_W + dq0) * SKS;
    const int  t1  = (dp1 * HALO_W + dq1) * SKS;
    const int  bt0 = dp0 * 13 + dq0;
    const int  bt1 = dp1 * 13 + dq1;
    const int  st0 = dp0 * 8 + dq0;
    const int  st1 = dp1 * 8 + dq1;

    float* seW = se + wid * 64;
    const float* sqW = sq + wid * 32;

    if (lane < 7) seW[lane * 8 + 7] = 0.f;   // zero pad slot (stays 0)
    __syncwarp();

    #pragma unroll
    for (int j = 0; j < TW; ++j) {
        const int w = w0 + j;
        int ws = w - 3; ws = ws < 0 ? 0 : (ws > 57 ? 57 : ws);
        const int rw = ws - gw0;

        const int pixoff = ((bbase + (h << 6) + w) << 7) + (nh << 5) + lane;
        sq[wid * 32 + lane] = g_q[pixoff];   // already *SCALE
        __syncwarp();

        const int base = (rh * HALO_W + rw) * SKS;
        const float* k0p = skf + base + t0;
        const float* k1p = skf + base + t1;
        float s0 = 0.f, s1 = 0.f;
        #pragma unroll
        for (int d4 = 0; d4 < 8; ++d4) {
            float4 q4 = *(const float4*)(sqW + d4 * 4);
            float4 a  = *(const float4*)(k0p + d4 * 4);
            float4 c4 = *(const float4*)(k1p + d4 * 4);
            s0 += q4.x * a.x  + q4.y * a.y  + q4.z * a.z  + q4.w * a.w;
            s1 += q4.x * c4.x + q4.y * c4.y + q4.z * c4.z + q4.w * c4.w;
        }

        const int bbb = (hs - h + 6) * 13 + (ws - w + 6);
        const float e0 = __expf(s0 + srp[bbb + bt0]);
        const float e1 = vd1 ? __expf(s1 + srp[bbb + bt1]) : 0.f;

        float l = e0 + e1;
        l += __shfl_xor_sync(0xffffffffu, l, 16);
        l += __shfl_xor_sync(0xffffffffu, l, 8);
        l += __shfl_xor_sync(0xffffffffu, l, 4);
        l += __shfl_xor_sync(0xffffffffu, l, 2);
        l += __shfl_xor_sync(0xffffffffu, l, 1);

        seW[st0] = e0;
        if (vd1) seW[st1] = e1;
        __syncwarp();

        float acc = 0.f;
        #pragma unroll
        for (int p = 0; p < KWIN; ++p) {
            const float* vr = svf + ((rh + p) * HALO_W + rw) * 32 + lane;
            float4 eA = *(const float4*)(seW + p * 8);
            float4 eB = *(const float4*)(seW + p * 8 + 4);
            acc += eA.x * vr[0]   + eA.y * vr[32]  + eA.z * vr[64]  + eA.w * vr[96]
                 + eB.x * vr[128] + eB.y * vr[160] + eB.z * vr[192];
        }
        g_att[pixoff] = acc / l;
        __syncwarp();
    }
}

extern "C" void kernel_launch(void* const* d_in, const int* in_sizes, int n_in,
                              void* d_out, int out_size) {
    (void)in_sizes; (void)n_in; (void)out_size;
    const float* x      = (const float*)d_in[0];
    const float* w_qkv  = (const float*)d_in[1];
    const float* b_qkv  = (const float*)d_in[2];
    const float* rpb    = (const float*)d_in[3];
    const float* w_proj = (const float*)d_in[4];
    const float* b_proj = (const float*)d_in[5];
    float* out = (float*)d_out;

    dim3 g1(MROWS / 128, 384 / 64);
    gemm_tc<384, 0><<<g1, 256>>>(x, w_qkv, b_qkv, nullptr);

    dim3 gn(WW / TW, (HH + TH - 1) / TH, BB * NHEAD);   // (8, 11, 8)
    natten_kernel<<<gn, 192>>>(rpb);

    dim3 g2(MROWS / 128, 128 / 64);
    gemm_tc<128, 1><<<g2, 256>>>(nullptr, w_proj, b_proj, out);
}

// round 7
// speedup vs baseline: 2.1334x; 1.0898x over previous
#include <cuda_runtime.h>

#define BB 2
#define HH 64
#define WW 64
#define CC 128
#define NHEAD 4
#define HD 32
#define KWIN 7
#define MROWS (BB*HH*WW)          /* 8192 */
#define SCALE 0.17677669529663687f /* 32^-0.5 */

// Scratch (allocation-free rule: device globals)
__device__ float g_q[MROWS*CC];
__device__ float g_k[MROWS*CC];
__device__ float g_v[MROWS*CC];
__device__ float g_att[MROWS*CC];

__device__ __forceinline__ unsigned f2tf(float f) {
    unsigned r;
    asm("cvt.rna.tf32.f32 %0, %1;" : "=r"(r) : "f"(f));
    return r;
}

__device__ __forceinline__ void mma_tf32(float c[4],
    unsigned a0, unsigned a1, unsigned a2, unsigned a3,
    unsigned b0, unsigned b1) {
    asm volatile(
        "mma.sync.aligned.m16n8k8.row.col.f32.tf32.tf32.f32 "
        "{%0,%1,%2,%3}, {%4,%5,%6,%7}, {%8,%9}, {%0,%1,%2,%3};"
        : "+f"(c[0]), "+f"(c[1]), "+f"(c[2]), "+f"(c[3])
        : "r"(a0), "r"(a1), "r"(a2), "r"(a3), "r"(b0), "r"(b1));
}

// ---------------------------------------------------------------------------
// tf32 tensor-core GEMM (unchanged from Round 6 — measured win).
// ---------------------------------------------------------------------------
template<int NTOT, int MODE>
__global__ __launch_bounds__(256)
void gemm_tc(const float* __restrict__ A,
             const float* __restrict__ W,
             const float* __restrict__ bias,
             float* __restrict__ out) {
    __shared__ __align__(16) unsigned As[128 * 36];  // [m][k], stride 36
    __shared__ __align__(16) unsigned Bs[32 * 72];   // [k][n], stride 72

    const float* Ap = (MODE == 1) ? (const float*)g_att : A;

    const int tid  = threadIdx.x;
    const int lane = tid & 31;
    const int wid  = tid >> 5;
    const int warpM = wid & 3;
    const int warpN = wid >> 2;
    const int grp = lane >> 2;
    const int tig = lane & 3;
    const int rowbase = blockIdx.x * 128;
    const int colbase = blockIdx.y * 64;

    float acc[2][4][4] = {};

    for (int kc = 0; kc < 4; ++kc) {
        const int k0 = kc * 32;
        #pragma unroll
        for (int j = 0; j < 4; ++j) {
            const int i = tid + j * 256;
            const int m  = i >> 3;
            const int kq = (i & 7) * 4;
            float4 v = *(const float4*)&Ap[(rowbase + m) * 128 + k0 + kq];
            uint4 u = make_uint4(f2tf(v.x), f2tf(v.y), f2tf(v.z), f2tf(v.w));
            *(uint4*)&As[m * 36 + kq] = u;
        }
        #pragma unroll
        for (int j = 0; j < 2; ++j) {
            const int i = tid + j * 256;
            const int k  = i >> 4;
            const int nq = (i & 15) * 4;
            float4 v = *(const float4*)&W[(k0 + k) * NTOT + colbase + nq];
            uint4 u = make_uint4(f2tf(v.x), f2tf(v.y), f2tf(v.z), f2tf(v.w));
            *(uint4*)&Bs[k * 72 + nq] = u;
        }
        __syncthreads();

        #pragma unroll
        for (int ks = 0; ks < 4; ++ks) {
            const int kk = ks * 8;
            unsigned a[2][4], b[4][2];
            #pragma unroll
            for (int mf = 0; mf < 2; ++mf) {
                const int r = warpM * 32 + mf * 16 + grp;
                a[mf][0] = As[r * 36 + kk + tig];
                a[mf][1] = As[(r + 8) * 36 + kk + tig];
                a[mf][2] = As[r * 36 + kk + tig + 4];
                a[mf][3] = As[(r + 8) * 36 + kk + tig + 4];
            }
            #pragma unroll
            for (int nf = 0; nf < 4; ++nf) {
                const int c = warpN * 32 + nf * 8 + grp;
                b[nf][0] = Bs[(kk + tig) * 72 + c];
                b[nf][1] = Bs[(kk + tig + 4) * 72 + c];
            }
            #pragma unroll
            for (int mf = 0; mf < 2; ++mf)
                #pragma unroll
                for (int nf = 0; nf < 4; ++nf)
                    mma_tf32(acc[mf][nf],
                             a[mf][0], a[mf][1], a[mf][2], a[mf][3],
                             b[nf][0], b[nf][1]);
        }
        __syncthreads();
    }

    const int comp      = colbase >> 7;
    const int innerbase = colbase & 127;
    #pragma unroll
    for (int mf = 0; mf < 2; ++mf) {
        #pragma unroll
        for (int nf = 0; nf < 4; ++nf) {
            const int colL = colbase + warpN * 32 + nf * 8 + tig * 2;
            const float bs0 = bias[colL];
            const float bs1 = bias[colL + 1];
            #pragma unroll
            for (int rr = 0; rr < 2; ++rr) {
                const int row = rowbase + warpM * 32 + mf * 16 + grp + rr * 8;
                float v0 = acc[mf][nf][rr * 2 + 0] + bs0;
                float v1 = acc[mf][nf][rr * 2 + 1] + bs1;
                if (MODE == 0) {
                    const int inner = innerbase + warpN * 32 + nf * 8 + tig * 2;
                    if (comp == 0) {
                        *(float2*)&g_q[row * CC + inner] = make_float2(v0 * SCALE, v1 * SCALE);
                    } else if (comp == 1) {
                        *(float2*)&g_k[row * CC + inner] = make_float2(v0, v1);
                    } else {
                        *(float2*)&g_v[row * CC + inner] = make_float2(v0, v1);
                    }
                } else {
                    *(float2*)&out[row * NTOT + colL] = make_float2(v0, v1);
                }
            }
        }
    }
}

// ---------------------------------------------------------------------------
// Neighborhood attention v4:
//  - TH=4 rows x TW=8 cols tile, 8 warps: 2 warps per pixel row, 4 queries
//    each (2x warp parallelism vs v3).
//  - No shfl reduction: softmax denominator summed from the broadcast e-values
//    already loaded in Phase B.
//  - Double-buffered per-warp e-arrays: 2 syncwarps per query.
//  - Split accumulator chains in both phases.
// ---------------------------------------------------------------------------
#define TH 4
#define TW 8
#define HALO_H 10
#define HALO_W 14
#define NHALO (HALO_H*HALO_W)   /* 140 */
#define SKS 36                  /* padded K row stride (floats) */
#define NWARP 8

__global__ __launch_bounds__(256)
void natten_kernel(const float* __restrict__ rpb) {
    __shared__ float4 skq[NHALO * 9];                    // K halo (stride 36)
    __shared__ float4 svq[NHALO * 8];                    // V halo (stride 32)
    __shared__ __align__(16) float srp[176];             // rpb (169 used)
    __shared__ __align__(16) float sq[NWARP * 32];       // per-warp query
    __shared__ __align__(16) float se[NWARP * 128];      // per-warp e, x2 buf

    float* skf = (float*)skq;
    float* svf = (float*)svq;

    const int tid  = threadIdx.x;
    const int lane = tid & 31;
    const int wid  = tid >> 5;
    const int row  = wid >> 1;      // 0..3
    const int half = wid & 1;       // 0..1 -> queries half*4..half*4+3

    const int w0 = blockIdx.x * TW;
    const int h0 = blockIdx.y * TH;
    const int nh = blockIdx.z & 3;
    const int b  = blockIdx.z >> 2;

    int gh0 = h0 - 3; gh0 = gh0 < 0 ? 0 : (gh0 > 64 - HALO_H ? 64 - HALO_H : gh0);
    int gw0 = w0 - 3; gw0 = gw0 < 0 ? 0 : (gw0 > 64 - HALO_W ? 64 - HALO_W : gw0);

    for (int i = tid; i < 169; i += 256) srp[i] = rpb[nh * 169 + i];

    const float4* gk4 = (const float4*)g_k;
    const float4* gv4 = (const float4*)g_v;
    const int bbase = b << 12;
    for (int i = tid; i < NHALO * 8; i += 256) {
        const int p = i >> 3;
        const int f = i & 7;
        const int r = p / HALO_W;
        const int c = p - r * HALO_W;
        const int gp = bbase + ((gh0 + r) << 6) + gw0 + c;   // pixel index
        const int goff = gp * 32 + nh * 8 + f;               // float4 index
        skq[p * 9 + f] = gk4[goff];
        svq[p * 8 + f] = gv4[goff];
    }
    __syncthreads();

    const int h = h0 + row;                 // always < 64 (64 % TH == 0)
    int hs = h - 3; hs = hs < 0 ? 0 : (hs > 57 ? 57 : hs);
    const int rh = hs - gh0;

    // Per-lane neighbor mapping
    const int  n1  = lane + 32;
    const bool vd1 = (n1 < 49);
    const int  dp0 = lane / 7,            dq0 = lane - dp0 * 7;
    const int  dp1 = vd1 ? n1 / 7 : 0;
    const int  dq1 = vd1 ? n1 - dp1 * 7 : 0;
    const int  t0  = (dp0 * HALO_W + dq0) * SKS;
    const int  t1  = (dp1 * HALO_W + dq1) * SKS;
    const int  bt0 = dp0 * 13 + dq0;
    const int  bt1 = dp1 * 13 + dq1;
    const int  st0 = dp0 * 8 + dq0;
    const int  st1 = dp1 * 8 + dq1;

    float* seB = se + wid * 128;            // two 64-float buffers
    const float* sqW = sq + wid * 32;

    if (lane < 7) {                          // zero pad slots, both buffers
        seB[lane * 8 + 7]      = 0.f;
        seB[64 + lane * 8 + 7] = 0.f;
    }

    const int j0 = half * 4;
    #pragma unroll
    for (int jj = 0; jj < 4; ++jj) {
        const int w = w0 + j0 + jj;
        int ws = w - 3; ws = ws < 0 ? 0 : (ws > 57 ? 57 : ws);
        const int rw = ws - gw0;

        const int pixoff = ((bbase + (h << 6) + w) << 7) + (nh << 5) + lane;
        sq[wid * 32 + lane] = g_q[pixoff];   // already *SCALE
        __syncwarp();

        // Phase A: two dot products per lane, split chains
        const int base = (rh * HALO_W + rw) * SKS;
        const float* k0p = skf + base + t0;
        const float* k1p = skf + base + t1;
        float s0a = 0.f, s0b = 0.f, s1a = 0.f, s1b = 0.f;
        #pragma unroll
        for (int d4 = 0; d4 < 8; d4 += 2) {
            float4 qA = *(const float4*)(sqW + d4 * 4);
            float4 qB = *(const float4*)(sqW + d4 * 4 + 4);
            float4 aA = *(const float4*)(k0p + d4 * 4);
            float4 aB = *(const float4*)(k0p + d4 * 4 + 4);
            float4 cA = *(const float4*)(k1p + d4 * 4);
            float4 cB = *(const float4*)(k1p + d4 * 4 + 4);
            s0a += qA.x * aA.x + qA.y * aA.y + qA.z * aA.z + qA.w * aA.w;
            s0b += qB.x * aB.x + qB.y * aB.y + qB.z * aB.z + qB.w * aB.w;
            s1a += qA.x * cA.x + qA.y * cA.y + qA.z * cA.z + qA.w * cA.w;
            s1b += qB.x * cB.x + qB.y * cB.y + qB.z * cB.z + qB.w * cB.w;
        }

        const int bbb = (hs - h + 6) * 13 + (ws - w + 6);
        const float e0 = __expf(s0a + s0b + srp[bbb + bt0]);
        const float e1 = vd1 ? __expf(s1a + s1b + srp[bbb + bt1]) : 0.f;

        float* seW = seB + (jj & 1) * 64;
        seW[st0] = e0;
        if (vd1) seW[st1] = e1;
        __syncwarp();

        // Phase B: lane = head dim; acc and denominator from broadcast e's
        float accA = 0.f, accB = 0.f, lA = 0.f, lB = 0.f;
        #pragma unroll
        for (int p = 0; p < KWIN; ++p) {
            const float* vr = svf + ((rh + p) * HALO_W + rw) * 32 + lane;
            float4 eA = *(const float4*)(seW + p * 8);
            float4 eB = *(const float4*)(seW + p * 8 + 4);
            accA += eA.x * vr[0]   + eA.y * vr[32]  + eA.z * vr[64]  + eA.w * vr[96];
            accB += eB.x * vr[128] + eB.y * vr[160] + eB.z * vr[192];
            lA   += eA.x + eA.y + eA.z + eA.w;
            lB   += eB.x + eB.y + eB.z;        // eB.w is the zero pad
        }
        g_att[pixoff] = (accA + accB) / (lA + lB);
    }
}

extern "C" void kernel_launch(void* const* d_in, const int* in_sizes, int n_in,
                              void* d_out, int out_size) {
    (void)in_sizes; (void)n_in; (void)out_size;
    const float* x      = (const float*)d_in[0];
    const float* w_qkv  = (const float*)d_in[1];
    const float* b_qkv  = (const float*)d_in[2];
    const float* rpb    = (const float*)d_in[3];
    const float* w_proj = (const float*)d_in[4];
    const float* b_proj = (const float*)d_in[5];
    float* out = (float*)d_out;

    dim3 g1(MROWS / 128, 384 / 64);
    gemm_tc<384, 0><<<g1, 256>>>(x, w_qkv, b_qkv, nullptr);

    dim3 gn(WW / TW, HH / TH, BB * NHEAD);   // (8, 16, 8)
    natten_kernel<<<gn, 256>>>(rpb);

    dim3 g2(MROWS / 128, 128 / 64);
    gemm_tc<128, 1><<<g2, 256>>>(nullptr, w_proj, b_proj, out);
}

// round 8
// speedup vs baseline: 2.6924x; 1.2620x over previous
#include <cuda_runtime.h>

#define BB 2
#define HH 64
#define WW 64
#define CC 128
#define NHEAD 4
#define HD 32
#define KWIN 7
#define MROWS (BB*HH*WW)          /* 8192 */
#define SCALE 0.17677669529663687f /* 32^-0.5 */

// Scratch (allocation-free rule: device globals)
__device__ float g_q[MROWS*CC];
__device__ float g_k[MROWS*CC];
__device__ float g_v[MROWS*CC];
__device__ float g_att[MROWS*CC];

__device__ __forceinline__ unsigned f2tf(float f) {
    unsigned r;
    asm("cvt.rna.tf32.f32 %0, %1;" : "=r"(r) : "f"(f));
    return r;
}

__device__ __forceinline__ void mma_tf32(float c[4],
    unsigned a0, unsigned a1, unsigned a2, unsigned a3,
    unsigned b0, unsigned b1) {
    asm volatile(
        "mma.sync.aligned.m16n8k8.row.col.f32.tf32.tf32.f32 "
        "{%0,%1,%2,%3}, {%4,%5,%6,%7}, {%8,%9}, {%0,%1,%2,%3};"
        : "+f"(c[0]), "+f"(c[1]), "+f"(c[2]), "+f"(c[3])
        : "r"(a0), "r"(a1), "r"(a2), "r"(a3), "r"(b0), "r"(b1));
}

// ---------------------------------------------------------------------------
// tf32 tensor-core GEMM (unchanged from Round 6 — measured win).
// ---------------------------------------------------------------------------
template<int NTOT, int MODE>
__global__ __launch_bounds__(256)
void gemm_tc(const float* __restrict__ A,
             const float* __restrict__ W,
             const float* __restrict__ bias,
             float* __restrict__ out) {
    __shared__ __align__(16) unsigned As[128 * 36];
    __shared__ __align__(16) unsigned Bs[32 * 72];

    const float* Ap = (MODE == 1) ? (const float*)g_att : A;

    const int tid  = threadIdx.x;
    const int lane = tid & 31;
    const int wid  = tid >> 5;
    const int warpM = wid & 3;
    const int warpN = wid >> 2;
    const int grp = lane >> 2;
    const int tig = lane & 3;
    const int rowbase = blockIdx.x * 128;
    const int colbase = blockIdx.y * 64;

    float acc[2][4][4] = {};

    for (int kc = 0; kc < 4; ++kc) {
        const int k0 = kc * 32;
        #pragma unroll
        for (int j = 0; j < 4; ++j) {
            const int i = tid + j * 256;
            const int m  = i >> 3;
            const int kq = (i & 7) * 4;
            float4 v = *(const float4*)&Ap[(rowbase + m) * 128 + k0 + kq];
            uint4 u = make_uint4(f2tf(v.x), f2tf(v.y), f2tf(v.z), f2tf(v.w));
            *(uint4*)&As[m * 36 + kq] = u;
        }
        #pragma unroll
        for (int j = 0; j < 2; ++j) {
            const int i = tid + j * 256;
            const int k  = i >> 4;
            const int nq = (i & 15) * 4;
            float4 v = *(const float4*)&W[(k0 + k) * NTOT + colbase + nq];
            uint4 u = make_uint4(f2tf(v.x), f2tf(v.y), f2tf(v.z), f2tf(v.w));
            *(uint4*)&Bs[k * 72 + nq] = u;
        }
        __syncthreads();

        #pragma unroll
        for (int ks = 0; ks < 4; ++ks) {
            const int kk = ks * 8;
            unsigned a[2][4], b[4][2];
            #pragma unroll
            for (int mf = 0; mf < 2; ++mf) {
                const int r = warpM * 32 + mf * 16 + grp;
                a[mf][0] = As[r * 36 + kk + tig];
                a[mf][1] = As[(r + 8) * 36 + kk + tig];
                a[mf][2] = As[r * 36 + kk + tig + 4];
                a[mf][3] = As[(r + 8) * 36 + kk + tig + 4];
            }
            #pragma unroll
            for (int nf = 0; nf < 4; ++nf) {
                const int c = warpN * 32 + nf * 8 + grp;
                b[nf][0] = Bs[(kk + tig) * 72 + c];
                b[nf][1] = Bs[(kk + tig + 4) * 72 + c];
            }
            #pragma unroll
            for (int mf = 0; mf < 2; ++mf)
                #pragma unroll
                for (int nf = 0; nf < 4; ++nf)
                    mma_tf32(acc[mf][nf],
                             a[mf][0], a[mf][1], a[mf][2], a[mf][3],
                             b[nf][0], b[nf][1]);
        }
        __syncthreads();
    }

    const int comp      = colbase >> 7;
    const int innerbase = colbase & 127;
    #pragma unroll
    for (int mf = 0; mf < 2; ++mf) {
        #pragma unroll
        for (int nf = 0; nf < 4; ++nf) {
            const int colL = colbase + warpN * 32 + nf * 8 + tig * 2;
            const float bs0 = bias[colL];
            const float bs1 = bias[colL + 1];
            #pragma unroll
            for (int rr = 0; rr < 2; ++rr) {
                const int row = rowbase + warpM * 32 + mf * 16 + grp + rr * 8;
                float v0 = acc[mf][nf][rr * 2 + 0] + bs0;
                float v1 = acc[mf][nf][rr * 2 + 1] + bs1;
                if (MODE == 0) {
                    const int inner = innerbase + warpN * 32 + nf * 8 + tig * 2;
                    if (comp == 0) {
                        *(float2*)&g_q[row * CC + inner] = make_float2(v0 * SCALE, v1 * SCALE);
                    } else if (comp == 1) {
                        *(float2*)&g_k[row * CC + inner] = make_float2(v0, v1);
                    } else {
                        *(float2*)&g_v[row * CC + inner] = make_float2(v0, v1);
                    }
                } else {
                    *(float2*)&out[row * NTOT + colL] = make_float2(v0, v1);
                }
            }
        }
    }
}

// ---------------------------------------------------------------------------
// Neighborhood attention v5: tensor-core attention.
// Block = 4(h) x 8(w) pixel tile x 1 head = 32 queries, 2 m16-tiles.
// 4 warps = (m-tile, n-half). Halo 10x14=140 px (pad 144) of K/V as tf32 in
// smem, stride 36 (conflict-free B fragments).
//   S[16x72] = Q @ K^T (36 mma), mask + rpb bias + exp in registers,
//   P relayout accum->A-fragment via shfl (no smem),
//   O[16x32] = P @ V (36 mma), denominators via 2 shfl + cross-half smem.
// m16 row r = pr*8+pc -> pixel (h0 + mt*2 + pr, w0 + pc); n = hr*14 + wc.
// Pad cols n in [140,144): kh = gh0+10 is always outside every window -> e=0;
// sV pad rows zeroed so 0 * garbage never makes NaN.
// ---------------------------------------------------------------------------
#define TTH 4
#define TTW 8
#define NHALO_H 10
#define NHALO_W 14
#define NPX 140
#define NPAD 144
#define SKSN 36

__global__ __launch_bounds__(128)
void natten_tc(const float* __restrict__ rpb) {
    __shared__ __align__(16) unsigned sK[NPAD * SKSN];
    __shared__ __align__(16) unsigned sV[NPAD * SKSN];
    __shared__ float srp[169];
    __shared__ float sl[2][2][16];

    const int tid  = threadIdx.x;
    const int lane = tid & 31;
    const int wid  = tid >> 5;     // 0..3
    const int mt   = wid >> 1;     // m-tile (pixel rows mt*2, mt*2+1)
    const int half = wid & 1;      // n-half: cols [half*72, half*72+72)
    const int grp  = lane >> 2;    // 0..7
    const int tig  = lane & 3;     // 0..3

    const int w0 = blockIdx.x * TTW;
    const int h0 = blockIdx.y * TTH;
    const int nh = blockIdx.z & 3;
    const int b  = blockIdx.z >> 2;
    const int bbase = b << 12;

    int gh0 = h0 - 3; gh0 = gh0 < 0 ? 0 : (gh0 > 64 - NHALO_H ? 64 - NHALO_H : gh0);
    int gw0 = w0 - 3; gw0 = gw0 < 0 ? 0 : (gw0 > 64 - NHALO_W ? 64 - NHALO_W : gw0);

    for (int i = tid; i < 169; i += 128) srp[i] = rpb[nh * 169 + i];

    // Stage K/V halo as tf32, [px][dim] stride 36
    const float4* gk4 = (const float4*)g_k;
    const float4* gv4 = (const float4*)g_v;
    for (int i = tid; i < NPX * 8; i += 128) {
        const int px = i >> 3;
        const int f  = i & 7;
        const int r  = px / NHALO_W;
        const int c  = px - r * NHALO_W;
        const int goff = (bbase + ((gh0 + r) << 6) + gw0 + c) * 32 + nh * 8 + f;
        float4 kv = gk4[goff];
        float4 vv = gv4[goff];
        *(uint4*)&sK[px * SKSN + f * 4] = make_uint4(f2tf(kv.x), f2tf(kv.y), f2tf(kv.z), f2tf(kv.w));
        *(uint4*)&sV[px * SKSN + f * 4] = make_uint4(f2tf(vv.x), f2tf(vv.y), f2tf(vv.z), f2tf(vv.w));
    }
    // Zero pad rows 140..143 (sV mandatory: 0 * garbage must stay 0)
    for (int i = tid; i < (NPAD - NPX) * SKSN; i += 128) {
        sK[NPX * SKSN + i] = 0;
        sV[NPX * SKSN + i] = 0;
    }
    __syncthreads();

    // Query pixels for this warp's m-tile: rows grp (pixA) and grp+8 (pixB)
    const int hA = h0 + mt * 2;
    const int hB = hA + 1;
    const int wq = w0 + grp;
    const int pixA = bbase + (hA << 6) + wq;
    const int pixB = pixA + 64;

    // Q A-fragments (from gmem, already *SCALE), per k-chunk kc: dims kc*8+{tig,tig+4}
    unsigned qa[4][4];
    #pragma unroll
    for (int kc = 0; kc < 4; ++kc) {
        const int d = kc * 8 + tig;
        qa[kc][0] = f2tf(g_q[pixA * CC + nh * 32 + d]);
        qa[kc][1] = f2tf(g_q[pixB * CC + nh * 32 + d]);
        qa[kc][2] = f2tf(g_q[pixA * CC + nh * 32 + d + 4]);
        qa[kc][3] = f2tf(g_q[pixB * CC + nh * 32 + d + 4]);
    }

    // S = Q @ K^T over this warp's 72 neighbor columns
    float sacc[9][4] = {};
    #pragma unroll
    for (int i = 0; i < 9; ++i) {
        const int n0 = half * 72 + i * 8;
        #pragma unroll
        for (int kc = 0; kc < 4; ++kc) {
            unsigned b0 = sK[(n0 + grp) * SKSN + kc * 8 + tig];
            unsigned b1 = sK[(n0 + grp) * SKSN + kc * 8 + tig + 4];
            mma_tf32(sacc[i], qa[kc][0], qa[kc][1], qa[kc][2], qa[kc][3], b0, b1);
        }
    }

    // Mask + bias + exp. sacc[i] layout: c0=(row grp, col n0+2t), c1=+1, c2/c3 rows grp+8
    int hsA = hA - 3; hsA = hsA < 0 ? 0 : (hsA > 57 ? 57 : hsA);
    int hsB = hB - 3; hsB = hsB < 0 ? 0 : (hsB > 57 ? 57 : hsB);
    int wsq = wq - 3; wsq = wsq < 0 ? 0 : (wsq > 57 ? 57 : wsq);

    float e[9][4];
    float lA = 0.f, lB = 0.f;
    #pragma unroll
    for (int i = 0; i < 9; ++i) {
        #pragma unroll
        for (int ee = 0; ee < 2; ++ee) {
            const int n  = half * 72 + i * 8 + 2 * tig + ee;
            const int hr = n / NHALO_W;
            const int wc = n - hr * NHALO_W;
            const int kh = gh0 + hr;
            const int kw = gw0 + wc;
            const bool vw = (kw >= wsq) && (kw <= wsq + 6);
            float eA = 0.f, eB = 0.f;
            if (vw && kh >= hsA && kh <= hsA + 6)
                eA = __expf(sacc[i][ee]     + srp[(kh - hA + 6) * 13 + (kw - wq + 6)]);
            if (vw && kh >= hsB && kh <= hsB + 6)
                eB = __expf(sacc[i][2 + ee] + srp[(kh - hB + 6) * 13 + (kw - wq + 6)]);
            e[i][ee]     = eA;
            e[i][2 + ee] = eB;
            lA += eA;
            lB += eB;
        }
    }
    // Row sums across the 4 tig lanes, then across the two n-half warps
    lA += __shfl_xor_sync(0xffffffffu, lA, 1);
    lA += __shfl_xor_sync(0xffffffffu, lA, 2);
    lB += __shfl_xor_sync(0xffffffffu, lB, 1);
    lB += __shfl_xor_sync(0xffffffffu, lB, 2);
    if (tig == 0) {
        sl[mt][half][grp]     = lA;
        sl[mt][half][grp + 8] = lB;
    }
    __syncthreads();
    const float invA = 1.f / (sl[mt][0][grp]     + sl[mt][1][grp]);
    const float invB = 1.f / (sl[mt][0][grp + 8] + sl[mt][1][grp + 8]);

    // O = P @ V over this warp's 72 neighbors (partial, summed via same-accum
    // across halves? No — halves hold disjoint k-ranges; combine below.)
    float oacc[4][4] = {};
    const int src0 = grp * 4 + (tig >> 1);
    const bool odd = tig & 1;
    #pragma unroll
    for (int i = 0; i < 9; ++i) {
        // Relayout accum-fragment e -> A-fragment P for neighbor chunk i
        float p0a = __shfl_sync(0xffffffffu, e[i][0], src0);
        float p0b = __shfl_sync(0xffffffffu, e[i][1], src0);
        float p1a = __shfl_sync(0xffffffffu, e[i][2], src0);
        float p1b = __shfl_sync(0xffffffffu, e[i][3], src0);
        float p2a = __shfl_sync(0xffffffffu, e[i][0], src0 + 2);
        float p2b = __shfl_sync(0xffffffffu, e[i][1], src0 + 2);
        float p3a = __shfl_sync(0xffffffffu, e[i][2], src0 + 2);
        float p3b = __shfl_sync(0xffffffffu, e[i][3], src0 + 2);
        unsigned a0 = f2tf(odd ? p0b : p0a);
        unsigned a1 = f2tf(odd ? p1b : p1a);
        unsigned a2 = f2tf(odd ? p2b : p2a);
        unsigned a3 = f2tf(odd ? p3b : p3a);
        const int kb = half * 72 + i * 8;
        #pragma unroll
        for (int dt = 0; dt < 4; ++dt) {
            unsigned b0 = sV[(kb + tig) * SKSN + dt * 8 + grp];
            unsigned b1 = sV[(kb + tig + 4) * SKSN + dt * 8 + grp];
            mma_tf32(oacc[dt], a0, a1, a2, a3, b0, b1);
        }
    }

    // Combine the two n-halves per m-tile: half 1 adds into half 0 via smem
    __shared__ __align__(16) float sO[2][16 * 32];
    #pragma unroll
    for (int dt = 0; dt < 4; ++dt) {
        const int dc = dt * 8 + tig * 2;
        if (half == 0) {
            sO[mt][grp * 32 + dc]            = oacc[dt][0];
            sO[mt][grp * 32 + dc + 1]        = oacc[dt][1];
            sO[mt][(grp + 8) * 32 + dc]      = oacc[dt][2];
            sO[mt][(grp + 8) * 32 + dc + 1]  = oacc[dt][3];
        }
    }
    __syncthreads();
    if (half == 1) {
        #pragma unroll
        for (int dt = 0; dt < 4; ++dt) {
            const int dc = dt * 8 + tig * 2;
            float t0 = oacc[dt][0] + sO[mt][grp * 32 + dc];
            float t1 = oacc[dt][1] + sO[mt][grp * 32 + dc + 1];
            float t2 = oacc[dt][2] + sO[mt][(grp + 8) * 32 + dc];
            float t3 = oacc[dt][3] + sO[mt][(grp + 8) * 32 + dc + 1];
            *(float2*)&g_att[pixA * CC + nh * 32 + dc] = make_float2(t0 * invA, t1 * invA);
            *(float2*)&g_att[pixB * CC + nh * 32 + dc] = make_float2(t2 * invB, t3 * invB);
        }
    }
}

extern "C" void kernel_launch(void* const* d_in, const int* in_sizes, int n_in,
                              void* d_out, int out_size) {
    (void)in_sizes; (void)n_in; (void)out_size;
    const float* x      = (const float*)d_in[0];
    const float* w_qkv  = (const float*)d_in[1];
    const float* b_qkv  = (const float*)d_in[2];
    const float* rpb    = (const float*)d_in[3];
    const float* w_proj = (const float*)d_in[4];
    const float* b_proj = (const float*)d_in[5];
    float* out = (float*)d_out;

    dim3 g1(MROWS / 128, 384 / 64);
    gemm_tc<384, 0><<<g1, 256>>>(x, w_qkv, b_qkv, nullptr);

    dim3 gn(WW / TTW, HH / TTH, BB * NHEAD);   // (8, 16, 8)
    natten_tc<<<gn, 128>>>(rpb);

    dim3 g2(MROWS / 128, 128 / 64);
    gemm_tc<128, 1><<<g2, 256>>>(nullptr, w_proj, b_proj, out);
}